// round 10
// baseline (speedup 1.0000x reference)
#include <cuda_runtime.h>

#define BATCH 64
#define NUM_SPEC 8
#define VOCAB 128000
#define ROWS 512
#define ROW_F4 32000
#define N_F4 16384000LL     // 512 * 32000 float4 total
#define THREADS 320
#define NWARPS (THREADS / 32)

// Device scratch (no allocation allowed). Zero-init at module load;
// reset to zero by the last CTA each launch (graph-replay deterministic).
__device__ unsigned long long g_key[ROWS];   // 0 == -inf sentinel
__device__ int g_done;

// Order-preserving float->uint map (no NaNs in randn logits).
__device__ __forceinline__ unsigned fmap(float v) {
    unsigned u = __float_as_uint(v);
    return (u & 0x80000000u) ? ~u : (u | 0x80000000u);
}

// Block reduce (max value, tie -> smaller index) then atomicMax-merge into row key.
__device__ __forceinline__ void reduce_and_commit(
    float best, int bidx, int row, float* sv, int* si)
{
    #pragma unroll
    for (int off = 16; off > 0; off >>= 1) {
        float ov = __shfl_down_sync(0xffffffffu, best, off);
        int   oi = __shfl_down_sync(0xffffffffu, bidx, off);
        if (ov > best || (ov == best && oi < bidx)) { best = ov; bidx = oi; }
    }
    const int w = threadIdx.x >> 5;
    if ((threadIdx.x & 31) == 0) { sv[w] = best; si[w] = bidx; }
    __syncthreads();
    if (threadIdx.x == 0) {
        #pragma unroll
        for (int j = 1; j < NWARPS; j++) {
            if (sv[j] > best || (sv[j] == best && si[j] < bidx)) {
                best = sv[j]; bidx = si[j];
            }
        }
        unsigned long long key =
            ((unsigned long long)fmap(best) << 32) |
            (unsigned long long)(0xFFFFFFFFu - (unsigned)bidx);
        atomicMax(&g_key[row], key);
    }
    __syncthreads();   // protect sv/si reuse by a second fragment
}

// Scan f4 range [fs, fe) of one row (rp = row base). Front-batched loads (MLP 8).
__device__ __forceinline__ void scan_frag(
    const float4* __restrict__ rp, int fs, int fe, int row, float* sv, int* si)
{
    float best = -3.402823466e+38f;
    int   bidx = 0;
    int i = fs + threadIdx.x;
    while (i + 7 * THREADS < fe) {
        float4 v[8];
        #pragma unroll
        for (int k = 0; k < 8; k++) v[k] = rp[i + k * THREADS];
        #pragma unroll
        for (int k = 0; k < 8; k++) {
            int e = (i + k * THREADS) * 4;
            if (v[k].x > best) { best = v[k].x; bidx = e; }
            if (v[k].y > best) { best = v[k].y; bidx = e + 1; }
            if (v[k].z > best) { best = v[k].z; bidx = e + 2; }
            if (v[k].w > best) { best = v[k].w; bidx = e + 3; }
        }
        i += 8 * THREADS;
    }
    for (; i < fe; i += THREADS) {
        float4 v = rp[i];
        int e = i * 4;
        if (v.x > best) { best = v.x; bidx = e; }
        if (v.y > best) { best = v.y; bidx = e + 1; }
        if (v.z > best) { best = v.z; bidx = e + 2; }
        if (v.w > best) { best = v.w; bidx = e + 3; }
    }
    reduce_and_commit(best, bidx, row, sv, si);
}

// ---------------------------------------------------------------------------
// Balanced persistent kernel: flat partition of all 16.384M float4 across
// gridDim.x CTAs (single full wave), per-row atomicMax merge, last-arriver
// epilogue. Output (float32):
//   [0 .. 576)   output_token_ids    [64][9]
//   [576 .. 640) num_rejected_tokens [64]
//   [640 .. 704) last_token_ids      [64]
// ---------------------------------------------------------------------------
__global__ void __launch_bounds__(THREADS, 6) fused_rejection_kernel(
    const float* __restrict__ logits,
    const int*   __restrict__ draft,    // [64][8]
    const int*   __restrict__ bonus,    // [64][1]
    float*       __restrict__ out)
{
    __shared__ float sv[NWARPS];
    __shared__ int   si[NWARPS];
    __shared__ int   s_last;

    const int g = gridDim.x;
    const long long start = N_F4 * blockIdx.x / g;
    const long long end   = N_F4 * (blockIdx.x + 1) / g;

    const int row0 = (int)(start / ROW_F4);
    const long long rb    = (long long)row0 * ROW_F4;
    const long long r0end = rb + ROW_F4;
    const float4* p = reinterpret_cast<const float4*>(logits);

    const long long eA = end < r0end ? end : r0end;
    scan_frag(p + rb, (int)(start - rb), (int)(eA - rb), row0, sv, si);
    if (end > r0end) {   // per-CTA range < ROW_F4, so at most one extra row
        scan_frag(p + r0end, 0, (int)(end - r0end), row0 + 1, sv, si);
    }

    __threadfence();
    if (threadIdx.x == 0) s_last = (atomicAdd(&g_done, 1) == g - 1);
    __syncthreads();

    if (s_last) {
        if (threadIdx.x == 0) g_done = 0;                 // reset for next replay
        const int b = threadIdx.x;
        if (b < BATCH) {
            int tt[NUM_SPEC];
            #pragma unroll
            for (int j = 0; j < NUM_SPEC; j++) {
                unsigned long long key = __ldcg(&g_key[b * NUM_SPEC + j]);
                tt[j] = (int)(0xFFFFFFFFu - (unsigned)(key & 0xFFFFFFFFull));
            }

            int num_accept = 0;
            bool prefix = true;
            #pragma unroll
            for (int j = 0; j < NUM_SPEC; j++) {
                if (prefix) {
                    if (draft[b * NUM_SPEC + j] == tt[j]) num_accept++;
                    else prefix = false;
                }
            }
            const bool all_acc  = (num_accept == NUM_SPEC);
            const int  keep_cnt = all_acc ? NUM_SPEC : (num_accept + 1);
            const int  bon      = bonus[b];

            #pragma unroll
            for (int j = 0; j < NUM_SPEC; j++) {
                out[b * (NUM_SPEC + 1) + j] = (j < keep_cnt) ? (float)tt[j] : -1.0f;
            }
            out[b * (NUM_SPEC + 1) + NUM_SPEC] = all_acc ? (float)bon : -1.0f;
            out[BATCH * (NUM_SPEC + 1) + b]    = (float)(NUM_SPEC - num_accept);
            out[BATCH * (NUM_SPEC + 1) + BATCH + b] =
                all_acc ? (float)bon : (float)tt[num_accept];
        }
        __syncthreads();   // all key reads done before reset
        for (int r = threadIdx.x; r < ROWS; r += THREADS) g_key[r] = 0ull;
    }
}

extern "C" void kernel_launch(void* const* d_in, const int* in_sizes, int n_in,
                              void* d_out, int out_size)
{
    const float* logits = (const float*)d_in[0];
    const int*   draft  = (const int*)d_in[1];
    const int*   bonus  = (const int*)d_in[2];
    float*       out    = (float*)d_out;

    int dev = 0, sms = 148;
    cudaGetDevice(&dev);
    cudaDeviceGetAttribute(&sms, cudaDevAttrMultiProcessorCount, dev);
    const int grid = sms * 6;   // exactly one full wave at occupancy 6

    fused_rejection_kernel<<<grid, THREADS>>>(logits, draft, bonus, out);
}

// round 13
// speedup vs baseline: 1.1503x; 1.1503x over previous
#include <cuda_runtime.h>

#define BATCH 64
#define NUM_SPEC 8
#define VOCAB 128000
#define ROWS 512
#define ROW_F4 32000
#define THREADS 320
#define NWARPS (THREADS / 32)
#define FULL_BATCHES 12     // 12*8 = 96 f4/thread
#define TAIL 4              // +4 = 100 f4/thread * 320 threads = 32000

// Device scratch (no allocation allowed). Plain per-row stores (one CTA owns
// a row), overwritten every launch -> no reset needed except the counter.
__device__ float g_val[ROWS];
__device__ int   g_idx[ROWS];
__device__ int   g_done;

// ---------------------------------------------------------------------------
// One CTA per row: static front-batched streaming loads (MLP 8), strict-> 
// first-occurrence argmax, warp+smem reduce, last-arriver fused epilogue.
// Output (float32):
//   [0 .. 576)   output_token_ids    [64][9]
//   [576 .. 640) num_rejected_tokens [64]
//   [640 .. 704) last_token_ids      [64]
// ---------------------------------------------------------------------------
__global__ void __launch_bounds__(THREADS, 6) fused_rejection_kernel(
    const float* __restrict__ logits,
    const int*   __restrict__ draft,    // [64][8]
    const int*   __restrict__ bonus,    // [64][1]
    float*       __restrict__ out)
{
    __shared__ float sv[NWARPS];
    __shared__ int   si[NWARPS];
    __shared__ int   s_last;

    const int row = blockIdx.x;
    const float4* __restrict__ p =
        reinterpret_cast<const float4*>(logits + (size_t)row * VOCAB);

    float best = -3.402823466e+38f;
    int   bidx = 0;

    // Indices visited in increasing order; strict > keeps first occurrence.
    int base = threadIdx.x;
    #pragma unroll 1
    for (int m = 0; m < FULL_BATCHES; m++) {
        float4 v[8];
        #pragma unroll
        for (int k = 0; k < 8; k++) v[k] = __ldcs(&p[base + k * THREADS]);
        #pragma unroll
        for (int k = 0; k < 8; k++) {
            int e = (base + k * THREADS) * 4;
            if (v[k].x > best) { best = v[k].x; bidx = e; }
            if (v[k].y > best) { best = v[k].y; bidx = e + 1; }
            if (v[k].z > best) { best = v[k].z; bidx = e + 2; }
            if (v[k].w > best) { best = v[k].w; bidx = e + 3; }
        }
        base += 8 * THREADS;
    }
    {   // static tail: 4 front-batched f4 per thread
        float4 v[TAIL];
        #pragma unroll
        for (int k = 0; k < TAIL; k++) v[k] = __ldcs(&p[base + k * THREADS]);
        #pragma unroll
        for (int k = 0; k < TAIL; k++) {
            int e = (base + k * THREADS) * 4;
            if (v[k].x > best) { best = v[k].x; bidx = e; }
            if (v[k].y > best) { best = v[k].y; bidx = e + 1; }
            if (v[k].z > best) { best = v[k].z; bidx = e + 2; }
            if (v[k].w > best) { best = v[k].w; bidx = e + 3; }
        }
    }

    // Warp reduce, tie-break toward smaller index.
    #pragma unroll
    for (int off = 16; off > 0; off >>= 1) {
        float ov = __shfl_down_sync(0xffffffffu, best, off);
        int   oi = __shfl_down_sync(0xffffffffu, bidx, off);
        if (ov > best || (ov == best && oi < bidx)) { best = ov; bidx = oi; }
    }
    const int w = threadIdx.x >> 5;
    if ((threadIdx.x & 31) == 0) { sv[w] = best; si[w] = bidx; }
    __syncthreads();

    if (threadIdx.x == 0) {
        #pragma unroll
        for (int j = 1; j < NWARPS; j++) {
            if (sv[j] > best || (sv[j] == best && si[j] < bidx)) {
                best = sv[j]; bidx = si[j];
            }
        }
        g_val[row] = best;
        g_idx[row] = bidx;
        __threadfence();
        s_last = (atomicAdd(&g_done, 1) == ROWS - 1);
    }
    __syncthreads();

    // Last-arriver CTA: epilogue with 64 parallel threads (one per batch).
    if (s_last) {
        __threadfence();                      // order reads after observed adds
        if (threadIdx.x == 0) g_done = 0;     // reset for next graph replay
        const int b = threadIdx.x;
        if (b < BATCH) {
            int tt[NUM_SPEC];
            #pragma unroll
            for (int j = 0; j < NUM_SPEC; j++) {
                tt[j] = __ldcg(&g_idx[b * NUM_SPEC + j]);
            }

            int num_accept = 0;
            bool prefix = true;
            #pragma unroll
            for (int j = 0; j < NUM_SPEC; j++) {
                if (prefix) {
                    if (draft[b * NUM_SPEC + j] == tt[j]) num_accept++;
                    else prefix = false;
                }
            }
            const bool all_acc  = (num_accept == NUM_SPEC);
            const int  keep_cnt = all_acc ? NUM_SPEC : (num_accept + 1);
            const int  bon      = bonus[b];

            #pragma unroll
            for (int j = 0; j < NUM_SPEC; j++) {
                out[b * (NUM_SPEC + 1) + j] = (j < keep_cnt) ? (float)tt[j] : -1.0f;
            }
            out[b * (NUM_SPEC + 1) + NUM_SPEC] = all_acc ? (float)bon : -1.0f;
            out[BATCH * (NUM_SPEC + 1) + b]    = (float)(NUM_SPEC - num_accept);
            out[BATCH * (NUM_SPEC + 1) + BATCH + b] =
                all_acc ? (float)bon : (float)tt[num_accept];
        }
    }
}

extern "C" void kernel_launch(void* const* d_in, const int* in_sizes, int n_in,
                              void* d_out, int out_size)
{
    const float* logits = (const float*)d_in[0];
    const int*   draft  = (const int*)d_in[1];
    const int*   bonus  = (const int*)d_in[2];
    float*       out    = (float*)d_out;

    fused_rejection_kernel<<<ROWS, THREADS>>>(logits, draft, bonus, out);
}